// round 1
// baseline (speedup 1.0000x reference)
#include <cuda_runtime.h>
#include <cstdint>

// Problem constants
// x:        (256, 4, 256)       f32
// neighbor: (256, 64, 4, 256)   f32
// W_att1:   (4, 256)
// W_att2:   (4, 256)
// W_conv:   (2048, 8, 256)
// out:      (256, 8, 256)  -> d_out[0 .. 524287]
// adj:      (256, 4, 256, 256) -> d_out[524288 .. ]

#define Bsz 256
#define Cc  4
#define Nn  64
#define Ff  256
#define Ktot 2048      // 2C*F
#define Otot 2048      // OC*OF
#define OUT_ELEMS (Bsz*Otot)          // 524288
#define ADJ_OFF   OUT_ELEMS

// ---------------- scratch (static device arrays; no allocation) -------------
__device__ __align__(16) float g_ybar[Bsz*Cc*Ff];     // 1 MB
__device__ __align__(16) float g_z[Bsz*Ktot];         // 2 MB  (z = [h ; x])
__device__ __align__(16) float g_out4[4*OUT_ELEMS];   // 8 MB  (split-K partials)

// ---------------- helpers ---------------------------------------------------
__device__ __forceinline__ float fsqrt_ap(float x) {
    float r; asm("sqrt.approx.f32 %0, %1;" : "=f"(r) : "f"(x)); return r;
}
__device__ __forceinline__ float frcp_ap(float x) {
    float r; asm("rcp.approx.f32 %0, %1;" : "=f"(r) : "f"(x)); return r;
}
__device__ __forceinline__ unsigned long long ffma2(unsigned long long a,
                                                    unsigned long long b,
                                                    unsigned long long c) {
    unsigned long long d;
    asm("fma.rn.f32x2 %0, %1, %2, %3;" : "=l"(d) : "l"(a), "l"(b), "l"(c));
    return d;
}
__device__ __forceinline__ unsigned long long bcast2(float v) {
    unsigned long long r; unsigned int u = __float_as_uint(v);
    asm("mov.b64 %0, {%1, %1};" : "=l"(r) : "r"(u));
    return r;
}
__device__ __forceinline__ void unpack2(unsigned long long v, float& lo, float& hi) {
    unsigned int a, b;
    asm("mov.b64 {%0, %1}, %2;" : "=r"(a), "=r"(b) : "l"(v));
    lo = __uint_as_float(a); hi = __uint_as_float(b);
}

// ==================== K1: attention scores, softmax, ybar, z(x-part) ========
// grid 256 (one block per batch b), 256 threads
__global__ __launch_bounds__(256) void k1_attn(
    const float* __restrict__ x, const float* __restrict__ nb,
    const float* __restrict__ W1, const float* __restrict__ W2)
{
    int b = blockIdx.x;
    int t = threadIdx.x;
    __shared__ float w2s[256];
    __shared__ float s2s[64];
    __shared__ float ws[64];
    __shared__ float red[256];
    __shared__ float s1sh;

    // ---- phase A: column sums of weights, x, and s1 partials
    float w1f = W1[t] + W1[256 + t] + W1[512 + t] + W1[768 + t];
    float w2f = W2[t] + W2[256 + t] + W2[512 + t] + W2[768 + t];
    w2s[t] = w2f;
    const float* xb = x + b * 1024;
    float x0 = xb[t], x1 = xb[256 + t], x2 = xb[512 + t], x3 = xb[768 + t];
    red[t] = (x0 + x1 + x2 + x3) * w1f;
    __syncthreads();
    #pragma unroll
    for (int s = 128; s > 0; s >>= 1) {
        if (t < s) red[t] += red[t + s];
        __syncthreads();
    }
    if (t == 0) s1sh = red[0];

    // ---- phase B: s2[n] per warp
    int w = t >> 5, lane = t & 31;
    const float* nbb = nb + (size_t)b * (Nn * Cc * Ff);
    #pragma unroll
    for (int q = 0; q < 8; q++) {
        int n = w * 8 + q;
        const float* p = nbb + n * 1024;
        float acc = 0.f;
        #pragma unroll
        for (int s = 0; s < 8; s++) {
            int f = lane + 32 * s;
            acc += (p[f] + p[256 + f] + p[512 + f] + p[768 + f]) * w2s[f];
        }
        #pragma unroll
        for (int o = 16; o > 0; o >>= 1) acc += __shfl_xor_sync(0xffffffffu, acc, o);
        if (lane == 0) s2s[n] = acc;
    }
    __syncthreads();

    // ---- phase C: softmax over n (warp 0)
    if (w == 0) {
        float s1 = s1sh;
        float t0 = s1 * s2s[lane];
        float t1 = s1 * s2s[lane + 32];
        float m = fmaxf(t0, t1);
        #pragma unroll
        for (int o = 16; o > 0; o >>= 1) m = fmaxf(m, __shfl_xor_sync(0xffffffffu, m, o));
        float e0 = __expf(t0 - m), e1 = __expf(t1 - m);
        float se = e0 + e1;
        #pragma unroll
        for (int o = 16; o > 0; o >>= 1) se += __shfl_xor_sync(0xffffffffu, se, o);
        float inv = frcp_ap(se);
        ws[lane] = e0 * inv;
        ws[lane + 32] = e1 * inv;
    }
    __syncthreads();

    // ---- phase D: ybar[c][f] = sum_n w[n]*nb[n][c][f]   (f = t)
    float a0 = 0.f, a1 = 0.f, a2 = 0.f, a3 = 0.f;
    #pragma unroll 4
    for (int n = 0; n < 64; n++) {
        float wn = ws[n];
        const float* p = nbb + n * 1024 + t;
        a0 = fmaf(wn, p[0],   a0);
        a1 = fmaf(wn, p[256], a1);
        a2 = fmaf(wn, p[512], a2);
        a3 = fmaf(wn, p[768], a3);
    }
    float* yb = g_ybar + b * 1024;
    yb[t] = a0; yb[256 + t] = a1; yb[512 + t] = a2; yb[768 + t] = a3;

    // z channels 4..7 = x
    float* zb = g_z + b * Ktot + 1024;
    zb[t] = x0; zb[256 + t] = x1; zb[512 + t] = x2; zb[768 + t] = x3;
}

// ==================== K2: adj + h ===========================================
// grid 256 blocks, 256 threads. Each block handles 4 (b,c) matrices;
// each thread owns 4 consecutive columns of one matrix (STG.128 adj writes).
__global__ __launch_bounds__(256) void k2_adj(
    const float* __restrict__ x, float* __restrict__ out)
{
    int g  = threadIdx.x >> 6;          // 0..3: which matrix in this block
    int lt = threadIdx.x & 63;          // 0..63
    int bc = blockIdx.x * 4 + g;        // 0..1023
    int j0 = lt * 4;

    __shared__ float2 xy[4][256];
    __shared__ float  us[4][256];

    const float* xp = x + bc * 256;
    const float* yp = g_ybar + bc * 256;
    float xj[4], yj[4];
    #pragma unroll
    for (int k = 0; k < 4; k++) {
        xj[k] = xp[j0 + k];
        yj[k] = yp[j0 + k];
        xy[g][j0 + k] = make_float2(xj[k], yj[k]);
    }
    __syncthreads();

    // pass 1: column sums of |g|
    float cs[4] = {0.f, 0.f, 0.f, 0.f};
    #pragma unroll 4
    for (int i = 0; i < 256; i++) {
        float2 p = xy[g][i];
        #pragma unroll
        for (int k = 0; k < 4; k++) {
            float v = p.x * yj[k] + p.y * xj[k];
            float r = fsqrt_ap(fmaxf(fabsf(v), 1e-8f));
            cs[k] += (v != 0.f) ? r : 0.f;
        }
    }
    float rc[4];
    #pragma unroll
    for (int k = 0; k < 4; k++) {
        rc[k] = frcp_ap(cs[k] + 1e-7f);
        us[g][j0 + k] = xj[k] * rc[k];
    }
    __syncthreads();

    // pass 2: adj writes + h accumulation (uses symmetry: h[j] = sum_i g[i,j]*u[i])
    float h[4] = {0.f, 0.f, 0.f, 0.f};
    float* adj = out + (size_t)ADJ_OFF + (size_t)bc * 65536 + j0;
    #pragma unroll 2
    for (int i = 0; i < 256; i++) {
        float2 p = xy[g][i];
        float ui = us[g][i];
        float4 o;
        float vv[4];
        #pragma unroll
        for (int k = 0; k < 4; k++) {
            float v = p.x * yj[k] + p.y * xj[k];
            float r = fsqrt_ap(fmaxf(fabsf(v), 1e-8f));
            float gg = (v != 0.f) ? copysignf(r, v) : 0.f;
            vv[k] = gg;
            h[k] = fmaf(gg, ui, h[k]);
        }
        o.x = vv[0] * rc[0]; o.y = vv[1] * rc[1];
        o.z = vv[2] * rc[2]; o.w = vv[3] * rc[3];
        *(float4*)(adj + i * 256) = o;
    }

    // z channels 0..3 = h
    int b = bc >> 2, c = bc & 3;
    float* zrow = g_z + b * Ktot + c * 256 + j0;
    #pragma unroll
    for (int k = 0; k < 4; k++) zrow[k] = h[k];
}

// ==================== K3: GEMM out = z @ Wconv^T (split-K=4, FFMA2) =========
// grid (16, 2, 4): N tiles of 128, M tiles of 128, K chunks of 512. 256 thr.
#define KSTEP 16
#define APAD 130
#define BPAD 132
__global__ __launch_bounds__(256) void k3_gemm(const float* __restrict__ Wc)
{
    __shared__ float As[KSTEP * APAD];   // [k][m], m-pairs contiguous
    __shared__ float Bs[KSTEP * BPAD];   // [k][n]

    int t = threadIdx.x;
    int n0 = blockIdx.x * 128;
    int m0 = blockIdx.y * 128;
    int kc0 = blockIdx.z * 512;

    int tx = t & 15;    // N dir
    int ty = t >> 4;    // M dir
    int mb = ty * 8;    // micro m base (4 pairs)
    int nb = tx * 8;    // micro n base (8 cols)

    unsigned long long acc[4][8];
    #pragma unroll
    for (int p = 0; p < 4; p++)
        #pragma unroll
        for (int j = 0; j < 8; j++) acc[p][j] = 0ull;

    for (int tile = 0; tile < 512 / KSTEP; tile++) {
        int kc = kc0 + tile * KSTEP;
        // load A tile (z): 128 x 16, float4 per thread x2
        #pragma unroll
        for (int it = 0; it < 2; it++) {
            int lin = t + 256 * it;
            int mloc = lin >> 2;
            int kq = lin & 3;
            float4 v = *(const float4*)(g_z + (size_t)(m0 + mloc) * Ktot + kc + kq * 4);
            As[(kq * 4 + 0) * APAD + mloc] = v.x;
            As[(kq * 4 + 1) * APAD + mloc] = v.y;
            As[(kq * 4 + 2) * APAD + mloc] = v.z;
            As[(kq * 4 + 3) * APAD + mloc] = v.w;
        }
        // load B tile (W_conv): 128 x 16
        #pragma unroll
        for (int it = 0; it < 2; it++) {
            int lin = t + 256 * it;
            int nloc = lin >> 2;
            int kq = lin & 3;
            float4 v = *(const float4*)(Wc + (size_t)(n0 + nloc) * Ktot + kc + kq * 4);
            Bs[(kq * 4 + 0) * BPAD + nloc] = v.x;
            Bs[(kq * 4 + 1) * BPAD + nloc] = v.y;
            Bs[(kq * 4 + 2) * BPAD + nloc] = v.z;
            Bs[(kq * 4 + 3) * BPAD + nloc] = v.w;
        }
        __syncthreads();

        #pragma unroll
        for (int k = 0; k < KSTEP; k++) {
            unsigned long long a[4];
            #pragma unroll
            for (int p = 0; p < 4; p++)
                a[p] = *(const unsigned long long*)&As[k * APAD + mb + 2 * p];
            float4 b0 = *(const float4*)&Bs[k * BPAD + nb];
            float4 b1 = *(const float4*)&Bs[k * BPAD + nb + 4];
            unsigned long long bb[8];
            bb[0] = bcast2(b0.x); bb[1] = bcast2(b0.y);
            bb[2] = bcast2(b0.z); bb[3] = bcast2(b0.w);
            bb[4] = bcast2(b1.x); bb[5] = bcast2(b1.y);
            bb[6] = bcast2(b1.z); bb[7] = bcast2(b1.w);
            #pragma unroll
            for (int p = 0; p < 4; p++)
                #pragma unroll
                for (int j = 0; j < 8; j++)
                    acc[p][j] = ffma2(a[p], bb[j], acc[p][j]);
        }
        __syncthreads();
    }

    // epilogue: write split-K slab
    float* slab = g_out4 + (size_t)blockIdx.z * OUT_ELEMS;
    #pragma unroll
    for (int p = 0; p < 4; p++) {
        int m = m0 + mb + 2 * p;
        #pragma unroll
        for (int j = 0; j < 8; j++) {
            float lo, hi;
            unpack2(acc[p][j], lo, hi);
            slab[(size_t)m * Otot + n0 + nb + j] = lo;
            slab[(size_t)(m + 1) * Otot + n0 + nb + j] = hi;
        }
    }
}

// ==================== K4: split-K reduce into d_out =========================
__global__ __launch_bounds__(256) void k4_reduce(float* __restrict__ out)
{
    int i = blockIdx.x * 256 + threadIdx.x;   // float4 index, 131072 total
    const float4* s = (const float4*)g_out4;
    float4 a = s[i];
    float4 b = s[i + OUT_ELEMS / 4];
    float4 c = s[i + 2 * (OUT_ELEMS / 4)];
    float4 d = s[i + 3 * (OUT_ELEMS / 4)];
    float4 r;
    r.x = a.x + b.x + c.x + d.x;
    r.y = a.y + b.y + c.y + d.y;
    r.z = a.z + b.z + c.z + d.z;
    r.w = a.w + b.w + c.w + d.w;
    ((float4*)out)[i] = r;
}

// ============================================================================
extern "C" void kernel_launch(void* const* d_in, const int* in_sizes, int n_in,
                              void* d_out, int out_size)
{
    const float* x  = (const float*)d_in[0];
    const float* nb = (const float*)d_in[1];
    const float* W1 = (const float*)d_in[2];
    const float* W2 = (const float*)d_in[3];
    const float* Wc = (const float*)d_in[4];
    float* out = (float*)d_out;

    k1_attn<<<Bsz, 256>>>(x, nb, W1, W2);
    k2_adj<<<Bsz, 256>>>(x, out);
    k3_gemm<<<dim3(16, 2, 4), 256>>>(Wc);
    k4_reduce<<<OUT_ELEMS / 4 / 256, 256>>>(out);
}

// round 6
// speedup vs baseline: 1.0463x; 1.0463x over previous
#include <cuda_runtime.h>
#include <cstdint>

// x:        (256, 4, 256)       f32
// neighbor: (256, 64, 4, 256)   f32
// W_att1:   (4, 256)
// W_att2:   (4, 256)
// W_conv:   (2048, 8, 256)
// out:      (256, 8, 256)  -> d_out[0 .. 524287]
// adj:      (256, 4, 256, 256) -> d_out[524288 .. ]

#define Bsz 256
#define Cc  4
#define Nn  64
#define Ff  256
#define Ktot 2048
#define Otot 2048
#define OUT_ELEMS (Bsz*Otot)
#define ADJ_OFF   OUT_ELEMS

__device__ __align__(16) float g_ybar[Bsz*Cc*Ff];     // 1 MB
__device__ __align__(16) float g_z[Bsz*Ktot];         // 2 MB
__device__ __align__(16) float g_out4[4*OUT_ELEMS];   // 8 MB split-K slabs

__device__ __forceinline__ float fsqrt_ap(float x) {
    float r; asm("sqrt.approx.f32 %0, %1;" : "=f"(r) : "f"(x)); return r;
}
__device__ __forceinline__ float frcp_ap(float x) {
    float r; asm("rcp.approx.f32 %0, %1;" : "=f"(r) : "f"(x)); return r;
}
__device__ __forceinline__ unsigned long long ffma2(unsigned long long a,
                                                    unsigned long long b,
                                                    unsigned long long c) {
    unsigned long long d;
    asm("fma.rn.f32x2 %0, %1, %2, %3;" : "=l"(d) : "l"(a), "l"(b), "l"(c));
    return d;
}
__device__ __forceinline__ unsigned long long bcast2(float v) {
    unsigned long long r; unsigned int u = __float_as_uint(v);
    asm("mov.b64 %0, {%1, %1};" : "=l"(r) : "r"(u));
    return r;
}
__device__ __forceinline__ void unpack2(unsigned long long v, float& lo, float& hi) {
    unsigned int a, b;
    asm("mov.b64 {%0, %1}, %2;" : "=r"(a), "=r"(b) : "l"(v));
    lo = __uint_as_float(a); hi = __uint_as_float(b);
}

// ==================== K1: scores, softmax, ybar, z(x-part) ==================
__global__ __launch_bounds__(256) void k1_attn(
    const float* __restrict__ x, const float* __restrict__ nb,
    const float* __restrict__ W1, const float* __restrict__ W2)
{
    int b = blockIdx.x;
    int t = threadIdx.x;
    __shared__ float w2s[256];
    __shared__ float s2s[64];
    __shared__ float ws[64];
    __shared__ float red[256];
    __shared__ float s1sh;

    float w1f = W1[t] + W1[256 + t] + W1[512 + t] + W1[768 + t];
    float w2f = W2[t] + W2[256 + t] + W2[512 + t] + W2[768 + t];
    w2s[t] = w2f;
    const float* xb = x + b * 1024;
    float x0 = xb[t], x1 = xb[256 + t], x2 = xb[512 + t], x3 = xb[768 + t];
    red[t] = (x0 + x1 + x2 + x3) * w1f;
    __syncthreads();
    #pragma unroll
    for (int s = 128; s > 0; s >>= 1) {
        if (t < s) red[t] += red[t + s];
        __syncthreads();
    }
    if (t == 0) s1sh = red[0];

    int w = t >> 5, lane = t & 31;
    const float* nbb = nb + (size_t)b * (Nn * Cc * Ff);
    #pragma unroll
    for (int q = 0; q < 8; q++) {
        int n = w * 8 + q;
        const float* p = nbb + n * 1024;
        float acc = 0.f;
        #pragma unroll
        for (int s = 0; s < 8; s++) {
            int f = lane + 32 * s;
            acc += (p[f] + p[256 + f] + p[512 + f] + p[768 + f]) * w2s[f];
        }
        #pragma unroll
        for (int o = 16; o > 0; o >>= 1) acc += __shfl_xor_sync(0xffffffffu, acc, o);
        if (lane == 0) s2s[n] = acc;
    }
    __syncthreads();

    if (w == 0) {
        float s1 = s1sh;
        float t0 = s1 * s2s[lane];
        float t1 = s1 * s2s[lane + 32];
        float m = fmaxf(t0, t1);
        #pragma unroll
        for (int o = 16; o > 0; o >>= 1) m = fmaxf(m, __shfl_xor_sync(0xffffffffu, m, o));
        float e0 = __expf(t0 - m), e1 = __expf(t1 - m);
        float se = e0 + e1;
        #pragma unroll
        for (int o = 16; o > 0; o >>= 1) se += __shfl_xor_sync(0xffffffffu, se, o);
        float inv = frcp_ap(se);
        ws[lane] = e0 * inv;
        ws[lane + 32] = e1 * inv;
    }
    __syncthreads();

    float a0 = 0.f, a1 = 0.f, a2 = 0.f, a3 = 0.f;
    #pragma unroll 4
    for (int n = 0; n < 64; n++) {
        float wn = ws[n];
        const float* p = nbb + n * 1024 + t;
        a0 = fmaf(wn, p[0],   a0);
        a1 = fmaf(wn, p[256], a1);
        a2 = fmaf(wn, p[512], a2);
        a3 = fmaf(wn, p[768], a3);
    }
    float* yb = g_ybar + b * 1024;
    yb[t] = a0; yb[256 + t] = a1; yb[512 + t] = a2; yb[768 + t] = a3;

    float* zb = g_z + b * Ktot + 1024;
    zb[t] = x0; zb[256 + t] = x1; zb[512 + t] = x2; zb[768 + t] = x3;
}

// ==================== K2: adj + h ===========================================
__global__ __launch_bounds__(256) void k2_adj(
    const float* __restrict__ x, float* __restrict__ out)
{
    int g  = threadIdx.x >> 6;
    int lt = threadIdx.x & 63;
    int bc = blockIdx.x * 4 + g;
    int j0 = lt * 4;

    __shared__ float2 xy[4][256];
    __shared__ float  us[4][256];

    const float* xp = x + bc * 256;
    const float* yp = g_ybar + bc * 256;
    float xj[4], yj[4];
    #pragma unroll
    for (int k = 0; k < 4; k++) {
        xj[k] = xp[j0 + k];
        yj[k] = yp[j0 + k];
        xy[g][j0 + k] = make_float2(xj[k], yj[k]);
    }
    __syncthreads();

    // pass 1: column sums of |g| (no zero-guard: measure-zero, sub-1e-4 effect)
    float cs[4] = {0.f, 0.f, 0.f, 0.f};
    #pragma unroll 4
    for (int i = 0; i < 256; i++) {
        float2 p = xy[g][i];
        #pragma unroll
        for (int k = 0; k < 4; k++) {
            float v = fmaf(p.y, xj[k], p.x * yj[k]);
            cs[k] += fsqrt_ap(fmaxf(fabsf(v), 1e-8f));
        }
    }
    float rc[4];
    #pragma unroll
    for (int k = 0; k < 4; k++) {
        rc[k] = frcp_ap(cs[k] + 1e-7f);
        us[g][j0 + k] = xj[k] * rc[k];
    }
    __syncthreads();

    // pass 2: adj writes + h accumulation (symmetry: h[j] = sum_i g[i,j]*u[i])
    float h[4] = {0.f, 0.f, 0.f, 0.f};
    float* adj = out + (size_t)ADJ_OFF + (size_t)bc * 65536 + j0;
    #pragma unroll 2
    for (int i = 0; i < 256; i++) {
        float2 p = xy[g][i];
        float ui = us[g][i];
        float4 o;
        float vv[4];
        #pragma unroll
        for (int k = 0; k < 4; k++) {
            float v = fmaf(p.y, xj[k], p.x * yj[k]);
            float r = fsqrt_ap(fmaxf(fabsf(v), 1e-8f));
            float gg = (v != 0.f) ? copysignf(r, v) : 0.f;
            vv[k] = gg;
            h[k] = fmaf(gg, ui, h[k]);
        }
        o.x = vv[0] * rc[0]; o.y = vv[1] * rc[1];
        o.z = vv[2] * rc[2]; o.w = vv[3] * rc[3];
        *(float4*)(adj + i * 256) = o;
    }

    int b = bc >> 2, c = bc & 3;
    float* zrow = g_z + b * Ktot + c * 256 + j0;
    #pragma unroll
    for (int k = 0; k < 4; k++) zrow[k] = h[k];
}

// ==================== K3: GEMM out = z @ Wc^T, 64x128 tiles, split-K=4 ======
// grid (16 N-tiles, 4 M-tiles, 4 K-chunks), 256 threads.
// micro: thread (tx 0..15, ty 0..15): rows m0+ty*4..+3, cols n0+tx*4..+3 and
// n0+64+tx*4..+3  (contiguous 4-col groups -> conflict-free LDS.128 on B).
#define KSTEP 16
#define APAD 68
#define BPAD 132
__global__ __launch_bounds__(256, 2) void k3_gemm(const float* __restrict__ Wc)
{
    __shared__ float As[KSTEP * APAD];   // [k][m] 64 wide
    __shared__ float Bs[KSTEP * BPAD];   // [k][n] 128 wide

    int t = threadIdx.x;
    int n0 = blockIdx.x * 128;
    int m0 = blockIdx.y * 64;
    int kc0 = blockIdx.z * 512;

    int tx = t & 15;
    int ty = t >> 4;
    int mb = ty * 4;          // 2 m-pairs
    int cA = tx * 4;          // first 4-col group
    int cB = 64 + tx * 4;     // second 4-col group

    unsigned long long acc[2][8];
    #pragma unroll
    for (int p = 0; p < 2; p++)
        #pragma unroll
        for (int j = 0; j < 8; j++) acc[p][j] = 0ull;

    for (int tile = 0; tile < 512 / KSTEP; tile++) {
        int kc = kc0 + tile * KSTEP;
        // A tile: 64 x 16 = 256 float4, one per thread
        {
            int mloc = t >> 2;
            int kq = t & 3;
            float4 v = *(const float4*)(g_z + (size_t)(m0 + mloc) * Ktot + kc + kq * 4);
            As[(kq * 4 + 0) * APAD + mloc] = v.x;
            As[(kq * 4 + 1) * APAD + mloc] = v.y;
            As[(kq * 4 + 2) * APAD + mloc] = v.z;
            As[(kq * 4 + 3) * APAD + mloc] = v.w;
        }
        // B tile: 128 x 16 = 512 float4, two per thread
        #pragma unroll
        for (int it = 0; it < 2; it++) {
            int lin = t + 256 * it;
            int nloc = lin >> 2;
            int kq = lin & 3;
            float4 v = *(const float4*)(Wc + (size_t)(n0 + nloc) * Ktot + kc + kq * 4);
            Bs[(kq * 4 + 0) * BPAD + nloc] = v.x;
            Bs[(kq * 4 + 1) * BPAD + nloc] = v.y;
            Bs[(kq * 4 + 2) * BPAD + nloc] = v.z;
            Bs[(kq * 4 + 3) * BPAD + nloc] = v.w;
        }
        __syncthreads();

        #pragma unroll
        for (int k = 0; k < KSTEP; k++) {
            unsigned long long a[2];
            a[0] = *(const unsigned long long*)&As[k * APAD + mb];
            a[1] = *(const unsigned long long*)&As[k * APAD + mb + 2];
            float4 b0 = *(const float4*)&Bs[k * BPAD + cA];
            float4 b1 = *(const float4*)&Bs[k * BPAD + cB];
            unsigned long long bb[8];
            bb[0] = bcast2(b0.x); bb[1] = bcast2(b0.y);
            bb[2] = bcast2(b0.z); bb[3] = bcast2(b0.w);
            bb[4] = bcast2(b1.x); bb[5] = bcast2(b1.y);
            bb[6] = bcast2(b1.z); bb[7] = bcast2(b1.w);
            #pragma unroll
            for (int p = 0; p < 2; p++)
                #pragma unroll
                for (int j = 0; j < 8; j++)
                    acc[p][j] = ffma2(a[p], bb[j], acc[p][j]);
        }
        __syncthreads();
    }

    // epilogue: float4 stores per row into split-K slab
    float* slab = g_out4 + (size_t)blockIdx.z * OUT_ELEMS;
    #pragma unroll
    for (int r = 0; r < 4; r++) {
        int p = r >> 1;
        bool hiHalf = (r & 1);
        float4 oA, oB;
        {
            float lo, hi;
            unpack2(acc[p][0], lo, hi); oA.x = hiHalf ? hi : lo;
            unpack2(acc[p][1], lo, hi); oA.y = hiHalf ? hi : lo;
            unpack2(acc[p][2], lo, hi); oA.z = hiHalf ? hi : lo;
            unpack2(acc[p][3], lo, hi); oA.w = hiHalf ? hi : lo;
            unpack2(acc[p][4], lo, hi); oB.x = hiHalf ? hi : lo;
            unpack2(acc[p][5], lo, hi); oB.y = hiHalf ? hi : lo;
            unpack2(acc[p][6], lo, hi); oB.z = hiHalf ? hi : lo;
            unpack2(acc[p][7], lo, hi); oB.w = hiHalf ? hi : lo;
        }
        size_t row = (size_t)(m0 + mb + r) * Otot;
        *(float4*)(slab + row + n0 + cA) = oA;
        *(float4*)(slab + row + n0 + cB) = oB;
    }
}

// ==================== K4: split-K reduce ====================================
__global__ __launch_bounds__(256) void k4_reduce(float* __restrict__ out)
{
    const float4* s = (const float4*)g_out4;
    #pragma unroll
    for (int it = 0; it < 2; it++) {
        int i = blockIdx.x * 512 + it * 256 + threadIdx.x;
        float4 a = s[i];
        float4 b = s[i + OUT_ELEMS / 4];
        float4 c = s[i + 2 * (OUT_ELEMS / 4)];
        float4 d = s[i + 3 * (OUT_ELEMS / 4)];
        float4 r;
        r.x = a.x + b.x + c.x + d.x;
        r.y = a.y + b.y + c.y + d.y;
        r.z = a.z + b.z + c.z + d.z;
        r.w = a.w + b.w + c.w + d.w;
        ((float4*)out)[i] = r;
    }
}

// ============================================================================
extern "C" void kernel_launch(void* const* d_in, const int* in_sizes, int n_in,
                              void* d_out, int out_size)
{
    const float* x  = (const float*)d_in[0];
    const float* nb = (const float*)d_in[1];
    const float* W1 = (const float*)d_in[2];
    const float* W2 = (const float*)d_in[3];
    const float* Wc = (const float*)d_in[4];
    float* out = (float*)d_out;

    k1_attn<<<Bsz, 256>>>(x, nb, W1, W2);
    k2_adj<<<Bsz, 256>>>(x, out);
    k3_gemm<<<dim3(16, 4, 4), 256>>>(Wc);
    k4_reduce<<<OUT_ELEMS / 4 / 512, 256>>>(out);
}

// round 15
// speedup vs baseline: 1.0656x; 1.0185x over previous
#include <cuda_runtime.h>
#include <cstdint>

// x:        (256, 4, 256)       f32
// neighbor: (256, 64, 4, 256)   f32
// W_att1:   (4, 256)
// W_att2:   (4, 256)
// W_conv:   (2048, 8, 256)
// out:      (256, 8, 256)  -> d_out[0 .. 524287]
// adj:      (256, 4, 256, 256) -> d_out[524288 .. ]

#define Bsz 256
#define Cc  4
#define Nn  64
#define Ff  256
#define Ktot 2048
#define Otot 2048
#define OUT_ELEMS (Bsz*Otot)
#define ADJ_OFF   OUT_ELEMS

__device__ __align__(16) float g_ybar[Bsz*Cc*Ff];     // 1 MB
__device__ __align__(16) float g_rc[Bsz*Cc*Ff];       // 1 MB (reciprocal colsums)
__device__ __align__(16) float g_z[Bsz*Ktot];         // 2 MB
__device__ __align__(16) float g_out4[4*OUT_ELEMS];   // 8 MB split-K slabs

__device__ __forceinline__ float fsqrt_ap(float x) {
    float r; asm("sqrt.approx.f32 %0, %1;" : "=f"(r) : "f"(x)); return r;
}
__device__ __forceinline__ float frcp_ap(float x) {
    float r; asm("rcp.approx.f32 %0, %1;" : "=f"(r) : "f"(x)); return r;
}
__device__ __forceinline__ unsigned long long ffma2(unsigned long long a,
                                                    unsigned long long b,
                                                    unsigned long long c) {
    unsigned long long d;
    asm("fma.rn.f32x2 %0, %1, %2, %3;" : "=l"(d) : "l"(a), "l"(b), "l"(c));
    return d;
}
__device__ __forceinline__ unsigned long long bcast2(float v) {
    unsigned long long r; unsigned int u = __float_as_uint(v);
    asm("mov.b64 %0, {%1, %1};" : "=l"(r) : "r"(u));
    return r;
}
__device__ __forceinline__ void unpack2(unsigned long long v, float& lo, float& hi) {
    unsigned int a, b;
    asm("mov.b64 {%0, %1}, %2;" : "=r"(a), "=r"(b) : "l"(v));
    lo = __uint_as_float(a); hi = __uint_as_float(b);
}

// ==== K1: scores, softmax, ybar, z(x-part), + fused colsum/rc (old pass-1) ==
__global__ __launch_bounds__(256) void k1_attn(
    const float* __restrict__ x, const float* __restrict__ nb,
    const float* __restrict__ W1, const float* __restrict__ W2)
{
    int b = blockIdx.x;
    int t = threadIdx.x;
    __shared__ float w2s[256];
    __shared__ float s2s[64];
    __shared__ float ws[64];
    __shared__ float red[256];
    __shared__ float s1sh;
    __shared__ float2 xys[4][256];

    float w1f = W1[t] + W1[256 + t] + W1[512 + t] + W1[768 + t];
    float w2f = W2[t] + W2[256 + t] + W2[512 + t] + W2[768 + t];
    w2s[t] = w2f;
    const float* xb = x + b * 1024;
    float x0 = xb[t], x1 = xb[256 + t], x2 = xb[512 + t], x3 = xb[768 + t];
    red[t] = (x0 + x1 + x2 + x3) * w1f;
    __syncthreads();
    #pragma unroll
    for (int s = 128; s > 0; s >>= 1) {
        if (t < s) red[t] += red[t + s];
        __syncthreads();
    }
    if (t == 0) s1sh = red[0];

    int w = t >> 5, lane = t & 31;
    const float* nbb = nb + (size_t)b * (Nn * Cc * Ff);
    #pragma unroll
    for (int q = 0; q < 8; q++) {
        int n = w * 8 + q;
        const float* p = nbb + n * 1024;
        float acc = 0.f;
        #pragma unroll
        for (int s = 0; s < 8; s++) {
            int f = lane + 32 * s;
            acc += (p[f] + p[256 + f] + p[512 + f] + p[768 + f]) * w2s[f];
        }
        #pragma unroll
        for (int o = 16; o > 0; o >>= 1) acc += __shfl_xor_sync(0xffffffffu, acc, o);
        if (lane == 0) s2s[n] = acc;
    }
    __syncthreads();

    if (w == 0) {
        float s1 = s1sh;
        float t0 = s1 * s2s[lane];
        float t1 = s1 * s2s[lane + 32];
        float m = fmaxf(t0, t1);
        #pragma unroll
        for (int o = 16; o > 0; o >>= 1) m = fmaxf(m, __shfl_xor_sync(0xffffffffu, m, o));
        float e0 = __expf(t0 - m), e1 = __expf(t1 - m);
        float se = e0 + e1;
        #pragma unroll
        for (int o = 16; o > 0; o >>= 1) se += __shfl_xor_sync(0xffffffffu, se, o);
        float inv = frcp_ap(se);
        ws[lane] = e0 * inv;
        ws[lane + 32] = e1 * inv;
    }
    __syncthreads();

    // ybar[c][t] = sum_n w[n]*nb[n][c][t]
    float a0 = 0.f, a1 = 0.f, a2 = 0.f, a3 = 0.f;
    #pragma unroll 4
    for (int n = 0; n < 64; n++) {
        float wn = ws[n];
        const float* p = nbb + n * 1024 + t;
        a0 = fmaf(wn, p[0],   a0);
        a1 = fmaf(wn, p[256], a1);
        a2 = fmaf(wn, p[512], a2);
        a3 = fmaf(wn, p[768], a3);
    }
    // stage (x,y) pairs for colsum phase
    xys[0][t] = make_float2(x0, a0);
    xys[1][t] = make_float2(x1, a1);
    xys[2][t] = make_float2(x2, a2);
    xys[3][t] = make_float2(x3, a3);

    float* yb = g_ybar + b * 1024;
    yb[t] = a0; yb[256 + t] = a1; yb[512 + t] = a2; yb[768 + t] = a3;
    float* zb = g_z + b * Ktot + 1024;
    zb[t] = x0; zb[256 + t] = x1; zb[512 + t] = x2; zb[768 + t] = x3;

    __syncthreads();

    // fused colsum (old k2 pass-1): thread t owns column t of each channel.
    // MUST use the same expression/rounding as k2's pass-2 recompute.
    float xjv[4] = {x0, x1, x2, x3};
    float yjv[4] = {a0, a1, a2, a3};
    #pragma unroll
    for (int c = 0; c < 4; c++) {
        float cs = 0.f;
        #pragma unroll 8
        for (int i = 0; i < 256; i++) {
            float2 p = xys[c][i];
            float v = fmaf(p.y, xjv[c], p.x * yjv[c]);
            cs += fsqrt_ap(fmaxf(fabsf(v), 1e-8f));
        }
        g_rc[b * 1024 + c * 256 + t] = frcp_ap(cs + 1e-7f);
    }
}

// ==================== K2: adj + h (single pass, write-bound) ================
__global__ __launch_bounds__(256) void k2_adj(
    const float* __restrict__ x, float* __restrict__ out)
{
    int g  = threadIdx.x >> 6;
    int lt = threadIdx.x & 63;
    int bc = blockIdx.x * 4 + g;
    int j0 = lt * 4;

    __shared__ float2 xy[4][256];
    __shared__ float  us[4][256];

    const float* xp = x + bc * 256;
    const float* yp = g_ybar + bc * 256;
    const float* rp = g_rc + bc * 256;
    float xj[4], yj[4], rc[4];
    #pragma unroll
    for (int k = 0; k < 4; k++) {
        xj[k] = xp[j0 + k];
        yj[k] = yp[j0 + k];
        rc[k] = rp[j0 + k];
        xy[g][j0 + k] = make_float2(xj[k], yj[k]);
        us[g][j0 + k] = xj[k] * rc[k];
    }
    __syncthreads();

    // single pass: adj writes + h accumulation (symmetry: h[j]=sum_i g[i,j]u[i])
    float h[4] = {0.f, 0.f, 0.f, 0.f};
    float* adj = out + (size_t)ADJ_OFF + (size_t)bc * 65536 + j0;
    #pragma unroll 2
    for (int i = 0; i < 256; i++) {
        float2 p = xy[g][i];
        float ui = us[g][i];
        float4 o;
        float vv[4];
        #pragma unroll
        for (int k = 0; k < 4; k++) {
            float v = fmaf(p.y, xj[k], p.x * yj[k]);
            float r = fsqrt_ap(fmaxf(fabsf(v), 1e-8f));
            float gg = (v != 0.f) ? copysignf(r, v) : 0.f;
            vv[k] = gg;
            h[k] = fmaf(gg, ui, h[k]);
        }
        o.x = vv[0] * rc[0]; o.y = vv[1] * rc[1];
        o.z = vv[2] * rc[2]; o.w = vv[3] * rc[3];
        *(float4*)(adj + i * 256) = o;
    }

    int b = bc >> 2, c = bc & 3;
    float* zrow = g_z + b * Ktot + c * 256 + j0;
    #pragma unroll
    for (int k = 0; k < 4; k++) zrow[k] = h[k];
}

// ==== K3: GEMM out = z @ Wc^T, 64x128 tiles, split-K=4, double-buffered =====
#define KSTEP 16
#define APAD 68
#define BPAD 132
__global__ __launch_bounds__(256, 2) void k3_gemm(const float* __restrict__ Wc)
{
    __shared__ float As[2][KSTEP * APAD];   // [k][m] 64 wide
    __shared__ float Bs[2][KSTEP * BPAD];   // [k][n] 128 wide

    int t = threadIdx.x;
    int n0 = blockIdx.x * 128;
    int m0 = blockIdx.y * 64;
    int kc0 = blockIdx.z * 512;

    int tx = t & 15;
    int ty = t >> 4;
    int mb = ty * 4;          // 2 m-pairs
    int cA = tx * 4;          // first 4-col group
    int cB = 64 + tx * 4;     // second 4-col group

    int ldRow = t >> 2;       // 0..63
    int kq4   = (t & 3) * 4;  // 0,4,8,12

    const float* aPtr  = g_z + (size_t)(m0 + ldRow) * Ktot + kc0 + kq4;
    const float* bPtr0 = Wc  + (size_t)(n0 + ldRow) * Ktot + kc0 + kq4;
    const float* bPtr1 = Wc  + (size_t)(n0 + 64 + ldRow) * Ktot + kc0 + kq4;

    // prologue: tile 0 -> buffer 0
    float4 rA  = *(const float4*)aPtr;
    float4 rB0 = *(const float4*)bPtr0;
    float4 rB1 = *(const float4*)bPtr1;
    As[0][(kq4 + 0) * APAD + ldRow] = rA.x;
    As[0][(kq4 + 1) * APAD + ldRow] = rA.y;
    As[0][(kq4 + 2) * APAD + ldRow] = rA.z;
    As[0][(kq4 + 3) * APAD + ldRow] = rA.w;
    Bs[0][(kq4 + 0) * BPAD + ldRow] = rB0.x;
    Bs[0][(kq4 + 1) * BPAD + ldRow] = rB0.y;
    Bs[0][(kq4 + 2) * BPAD + ldRow] = rB0.z;
    Bs[0][(kq4 + 3) * BPAD + ldRow] = rB0.w;
    Bs[0][(kq4 + 0) * BPAD + 64 + ldRow] = rB1.x;
    Bs[0][(kq4 + 1) * BPAD + 64 + ldRow] = rB1.y;
    Bs[0][(kq4 + 2) * BPAD + 64 + ldRow] = rB1.z;
    Bs[0][(kq4 + 3) * BPAD + 64 + ldRow] = rB1.w;
    __syncthreads();

    unsigned long long acc[2][8];
    #pragma unroll
    for (int p = 0; p < 2; p++)
        #pragma unroll
        for (int j = 0; j < 8; j++) acc[p][j] = 0ull;

    #pragma unroll 1
    for (int tile = 0; tile < 32; tile++) {
        int cur = tile & 1;
        // prefetch next tile into registers (latency overlapped with compute)
        if (tile < 31) {
            aPtr  += KSTEP; bPtr0 += KSTEP; bPtr1 += KSTEP;
            rA  = *(const float4*)aPtr;
            rB0 = *(const float4*)bPtr0;
            rB1 = *(const float4*)bPtr1;
        }
        const float* Ac = As[cur];
        const float* Bc = Bs[cur];
        #pragma unroll
        for (int k = 0; k < KSTEP; k++) {
            unsigned long long a[2];
            a[0] = *(const unsigned long long*)&Ac[k * APAD + mb];
            a[1] = *(const unsigned long long*)&Ac[k * APAD + mb + 2];
            float4 b0 = *(const float4*)&Bc[k * BPAD + cA];
            float4 b1 = *(const float4*)&Bc[k * BPAD + cB];
            unsigned long long bb[8];
            bb[0] = bcast2(b0.x); bb[1] = bcast2(b0.y);
            bb[2] = bcast2(b0.z); bb[3] = bcast2(b0.w);
            bb[4] = bcast2(b1.x); bb[5] = bcast2(b1.y);
            bb[6] = bcast2(b1.z); bb[7] = bcast2(b1.w);
            #pragma unroll
            for (int p = 0; p < 2; p++)
                #pragma unroll
                for (int j = 0; j < 8; j++)
                    acc[p][j] = ffma2(a[p], bb[j], acc[p][j]);
        }
        if (tile < 31) {
            int nxt = cur ^ 1;
            As[nxt][(kq4 + 0) * APAD + ldRow] = rA.x;
            As[nxt][(kq4 + 1) * APAD + ldRow] = rA.y;
            As[nxt][(kq4 + 2) * APAD + ldRow] = rA.z;
            As[nxt][(kq4 + 3) * APAD + ldRow] = rA.w;
            Bs[nxt][(kq4 + 0) * BPAD + ldRow] = rB0.x;
            Bs[nxt][(kq4 + 1) * BPAD + ldRow] = rB0.y;
            Bs[nxt][(kq4 + 2) * BPAD + ldRow] = rB0.z;
            Bs[nxt][(kq4 + 3) * BPAD + ldRow] = rB0.w;
            Bs[nxt][(kq4 + 0) * BPAD + 64 + ldRow] = rB1.x;
            Bs[nxt][(kq4 + 1) * BPAD + 64 + ldRow] = rB1.y;
            Bs[nxt][(kq4 + 2) * BPAD + 64 + ldRow] = rB1.z;
            Bs[nxt][(kq4 + 3) * BPAD + 64 + ldRow] = rB1.w;
        }
        __syncthreads();
    }

    // epilogue: float4 stores per row into split-K slab
    float* slab = g_out4 + (size_t)blockIdx.z * OUT_ELEMS;
    #pragma unroll
    for (int r = 0; r < 4; r++) {
        int p = r >> 1;
        bool hiHalf = (r & 1);
        float4 oA, oB;
        {
            float lo, hi;
            unpack2(acc[p][0], lo, hi); oA.x = hiHalf ? hi : lo;
            unpack2(acc[p][1], lo, hi); oA.y = hiHalf ? hi : lo;
            unpack2(acc[p][2], lo, hi); oA.z = hiHalf ? hi : lo;
            unpack2(acc[p][3], lo, hi); oA.w = hiHalf ? hi : lo;
            unpack2(acc[p][4], lo, hi); oB.x = hiHalf ? hi : lo;
            unpack2(acc[p][5], lo, hi); oB.y = hiHalf ? hi : lo;
            unpack2(acc[p][6], lo, hi); oB.z = hiHalf ? hi : lo;
            unpack2(acc[p][7], lo, hi); oB.w = hiHalf ? hi : lo;
        }
        size_t row = (size_t)(m0 + mb + r) * Otot;
        *(float4*)(slab + row + n0 + cA) = oA;
        *(float4*)(slab + row + n0 + cB) = oB;
    }
}

// ==================== K4: split-K reduce (all loads first, MLP=8) ===========
__global__ __launch_bounds__(256) void k4_reduce(float* __restrict__ out)
{
    const float4* s = (const float4*)g_out4;
    int i0 = blockIdx.x * 512 + threadIdx.x;
    int i1 = i0 + 256;
    const int Q = OUT_ELEMS / 4;
    float4 a0 = s[i0], b0 = s[i0 + Q], c0 = s[i0 + 2 * Q], d0 = s[i0 + 3 * Q];
    float4 a1 = s[i1], b1 = s[i1 + Q], c1 = s[i1 + 2 * Q], d1 = s[i1 + 3 * Q];
    float4 r0, r1;
    r0.x = a0.x + b0.x + c0.x + d0.x;
    r0.y = a0.y + b0.y + c0.y + d0.y;
    r0.z = a0.z + b0.z + c0.z + d0.z;
    r0.w = a0.w + b0.w + c0.w + d0.w;
    r1.x = a1.x + b1.x + c1.x + d1.x;
    r1.y = a1.y + b1.y + c1.y + d1.y;
    r1.z = a1.z + b1.z + c1.z + d1.z;
    r1.w = a1.w + b1.w + c1.w + d1.w;
    ((float4*)out)[i0] = r0;
    ((float4*)out)[i1] = r1;
}

// ============================================================================
extern "C" void kernel_launch(void* const* d_in, const int* in_sizes, int n_in,
                              void* d_out, int out_size)
{
    const float* x  = (const float*)d_in[0];
    const float* nb = (const float*)d_in[1];
    const float* W1 = (const float*)d_in[2];
    const float* W2 = (const float*)d_in[3];
    const float* Wc = (const float*)d_in[4];
    float* out = (float*)d_out;

    k1_attn<<<Bsz, 256>>>(x, nb, W1, W2);
    k2_adj<<<Bsz, 256>>>(x, out);
    k3_gemm<<<dim3(16, 4, 4), 256>>>(Wc);
    k4_reduce<<<OUT_ELEMS / 4 / 512, 256>>>(out);
}